// round 8
// baseline (speedup 1.0000x reference)
#include <cuda_runtime.h>
#include <cuda_bf16.h>
#include <cstdint>

// Problem constants (fixed-shape benchmark)
#define N_NODES 50000
#define N_EDGES 800000
#define IN_DIM  512
#define HID_DIM 256
#define FDIM    256   // HID_DIM == OUT_DIM == 256

// ---------------------------------------------------------------------------
// Scratch (static __device__ — no allocation allowed)
// ---------------------------------------------------------------------------
__device__ __align__(128) float g_h[(size_t)N_NODES * FDIM];    // linear output of current layer
__device__ __align__(128) float g_agg[(size_t)N_NODES * FDIM];  // aggregated output of current layer
__device__ __align__(128) float g_dis[N_NODES];                 // deg^{-1/2}
__device__ int   g_deg[N_NODES];
__device__ int   g_off[N_NODES + 1];      // CSR row offsets (by dst)
__device__ int   g_cursor[N_NODES];       // placement cursors
__device__ int   g_csr_src[N_EDGES];
__device__ float g_csr_coef[N_EDGES];

// ---------------------------------------------------------------------------
// CSR construction (cold path; runs once per launch, tiny vs GEMMs)
// edge_index is INT32 (JAX default x64-disabled): ei[0:E)=src, ei[E:2E)=dst
// ---------------------------------------------------------------------------
__global__ void k_zero_deg() {
    int i = blockIdx.x * blockDim.x + threadIdx.x;
    if (i < N_NODES) g_deg[i] = 0;
}

__global__ void k_count_deg(const int* __restrict__ ei) {
    int e = blockIdx.x * blockDim.x + threadIdx.x;
    if (e < N_EDGES) {
        int d = ei[N_EDGES + e];
        if ((unsigned)d < (unsigned)N_NODES)   // defensive: degrade to wrong-answer, not fault
            atomicAdd(&g_deg[d], 1);
    }
}

// Single-block exclusive prefix sum over g_deg; also computes g_dis.
__global__ __launch_bounds__(1024) void k_scan() {
    __shared__ int s[1024];
    __shared__ int carry_s;
    if (threadIdx.x == 0) carry_s = 0;
    __syncthreads();
    for (int base = 0; base < N_NODES; base += 1024) {
        int i = base + threadIdx.x;
        int v = (i < N_NODES) ? g_deg[i] : 0;
        s[threadIdx.x] = v;
        __syncthreads();
        #pragma unroll
        for (int ofs = 1; ofs < 1024; ofs <<= 1) {
            int t = (threadIdx.x >= ofs) ? s[threadIdx.x - ofs] : 0;
            __syncthreads();
            s[threadIdx.x] += t;
            __syncthreads();
        }
        if (i < N_NODES) {
            int excl = carry_s + s[threadIdx.x] - v;   // exclusive scan value
            g_off[i]    = excl;
            g_cursor[i] = excl;
            g_dis[i]    = rsqrtf((float)v + 1.0f);
        }
        __syncthreads();
        if (threadIdx.x == 0) carry_s += s[1023];
        __syncthreads();
    }
    if (threadIdx.x == 0) g_off[N_NODES] = carry_s;   // == N_EDGES
}

__global__ void k_place(const int* __restrict__ ei) {
    int e = blockIdx.x * blockDim.x + threadIdx.x;
    if (e < N_EDGES) {
        int s = ei[e];
        int d = ei[N_EDGES + e];
        if ((unsigned)s >= (unsigned)N_NODES || (unsigned)d >= (unsigned)N_NODES) return;
        int pos = atomicAdd(&g_cursor[d], 1);
        g_csr_src[pos]  = s;
        g_csr_coef[pos] = g_dis[s] * g_dis[d];
    }
}

// ---------------------------------------------------------------------------
// Aggregation (gather, no atomics, deterministic):
// agg[i,f] = dis[i]^2 * h[i,f] + b[f] + sum_{e: dst=i} coef_e * h[src_e, f]
// One block per node, one thread per feature.
// ---------------------------------------------------------------------------
__global__ __launch_bounds__(FDIM) void k_aggregate(const float* __restrict__ bias) {
    const int i = blockIdx.x;
    const int f = threadIdx.x;
    const float di = g_dis[i];
    float acc = fmaf(di * di, g_h[(size_t)i * FDIM + f], bias[f]);
    const int e0 = g_off[i];
    const int e1 = g_off[i + 1];
    int e = e0;
    // 2-way unrolled gather to expose memory-level parallelism
    for (; e + 1 < e1; e += 2) {
        int   s0 = g_csr_src[e],      s1 = g_csr_src[e + 1];
        float c0 = g_csr_coef[e],     c1 = g_csr_coef[e + 1];
        float v0 = g_h[(size_t)s0 * FDIM + f];
        float v1 = g_h[(size_t)s1 * FDIM + f];
        acc = fmaf(c0, v0, acc);
        acc = fmaf(c1, v1, acc);
    }
    if (e < e1) {
        acc = fmaf(g_csr_coef[e], g_h[(size_t)g_csr_src[e] * FDIM + f], acc);
    }
    g_agg[(size_t)i * FDIM + f] = acc;
}

// ---------------------------------------------------------------------------
// Tiled fp32 GEMM: C[M=50000, N=256] = op(A) @ B (+ bias)
// BM=BN=64, BK=16, 256 threads, 4x4 per thread.
// AMODE: 0 = A param, 1 = A is g_agg.  CMODE: 0 = C is g_h, 1 = C param.
// RELU applies relu to A elements on load.
// ---------------------------------------------------------------------------
template<int AMODE, int CMODE, bool RELU, bool BIAS>
__global__ __launch_bounds__(256) void k_gemm64(
    const float* __restrict__ Ap, const float* __restrict__ B,
    const float* __restrict__ bias, float* __restrict__ Cp, int K)
{
    const float* A = (AMODE == 0) ? Ap : g_agg;
    float*       C = (CMODE == 0) ? g_h : Cp;
    const int M = N_NODES;
    const int N = FDIM;

    __shared__ float As[16][64];
    __shared__ float Bs[16][64];

    const int tid = threadIdx.x;
    const int tx = tid & 15;
    const int ty = tid >> 4;
    const int m0 = blockIdx.y * 64;
    const int n0 = blockIdx.x * 64;

    const int ar = tid >> 2;
    const int ak = (tid & 3) * 4;
    const int bk = tid >> 4;
    const int bc = (tid & 15) * 4;

    float acc[4][4] = {};

    for (int k0 = 0; k0 < K; k0 += 16) {
        float4 av = make_float4(0.f, 0.f, 0.f, 0.f);
        int arow = m0 + ar;
        if (arow < M)
            av = *reinterpret_cast<const float4*>(&A[(size_t)arow * K + k0 + ak]);
        if (RELU) {
            av.x = fmaxf(av.x, 0.f); av.y = fmaxf(av.y, 0.f);
            av.z = fmaxf(av.z, 0.f); av.w = fmaxf(av.w, 0.f);
        }
        As[ak + 0][ar] = av.x;
        As[ak + 1][ar] = av.y;
        As[ak + 2][ar] = av.z;
        As[ak + 3][ar] = av.w;

        *reinterpret_cast<float4*>(&Bs[bk][bc]) =
            *reinterpret_cast<const float4*>(&B[(size_t)(k0 + bk) * N + n0 + bc]);

        __syncthreads();

        #pragma unroll
        for (int kk = 0; kk < 16; kk++) {
            float4 a = *reinterpret_cast<const float4*>(&As[kk][ty * 4]);
            float4 b = *reinterpret_cast<const float4*>(&Bs[kk][tx * 4]);
            acc[0][0] = fmaf(a.x, b.x, acc[0][0]);
            acc[0][1] = fmaf(a.x, b.y, acc[0][1]);
            acc[0][2] = fmaf(a.x, b.z, acc[0][2]);
            acc[0][3] = fmaf(a.x, b.w, acc[0][3]);
            acc[1][0] = fmaf(a.y, b.x, acc[1][0]);
            acc[1][1] = fmaf(a.y, b.y, acc[1][1]);
            acc[1][2] = fmaf(a.y, b.z, acc[1][2]);
            acc[1][3] = fmaf(a.y, b.w, acc[1][3]);
            acc[2][0] = fmaf(a.z, b.x, acc[2][0]);
            acc[2][1] = fmaf(a.z, b.y, acc[2][1]);
            acc[2][2] = fmaf(a.z, b.z, acc[2][2]);
            acc[2][3] = fmaf(a.z, b.w, acc[2][3]);
            acc[3][0] = fmaf(a.w, b.x, acc[3][0]);
            acc[3][1] = fmaf(a.w, b.y, acc[3][1]);
            acc[3][2] = fmaf(a.w, b.z, acc[3][2]);
            acc[3][3] = fmaf(a.w, b.w, acc[3][3]);
        }
        __syncthreads();
    }

    float4 bb = make_float4(0.f, 0.f, 0.f, 0.f);
    if (BIAS) bb = *reinterpret_cast<const float4*>(&bias[n0 + tx * 4]);

    #pragma unroll
    for (int i = 0; i < 4; i++) {
        int row = m0 + ty * 4 + i;
        if (row < M) {
            float4 o;
            o.x = acc[i][0] + bb.x;
            o.y = acc[i][1] + bb.y;
            o.z = acc[i][2] + bb.z;
            o.w = acc[i][3] + bb.w;
            *reinterpret_cast<float4*>(&C[(size_t)row * FDIM + n0 + tx * 4]) = o;
        }
    }
}

// ---------------------------------------------------------------------------
// Launch — kernel launches ONLY (graph-capturable, allocation-free)
// ---------------------------------------------------------------------------
extern "C" void kernel_launch(void* const* d_in, const int* in_sizes, int n_in,
                              void* d_out, int out_size)
{
    const float* x  = (const float*)d_in[0];
    const int*   ei = (const int*)d_in[1];     // int32! (JAX x64 disabled)
    const float* W1 = (const float*)d_in[2];
    const float* b1 = (const float*)d_in[3];
    const float* W2 = (const float*)d_in[4];
    const float* b2 = (const float*)d_in[5];
    const float* Wp = (const float*)d_in[6];
    const float* bp = (const float*)d_in[7];
    float* out = (float*)d_out;

    const int TB = 256;
    const int nodeBlocks = (N_NODES + TB - 1) / TB;
    const int edgeBlocks = (N_EDGES + TB - 1) / TB;
    dim3 gemmGrid(FDIM / 64, (N_NODES + 63) / 64);

    // CSR build (by dst) + normalization coefficients
    k_zero_deg<<<nodeBlocks, TB>>>();
    k_count_deg<<<edgeBlocks, TB>>>(ei);
    k_scan<<<1, 1024>>>();
    k_place<<<edgeBlocks, TB>>>(ei);

    // Layer 1: h = x @ W1 ; agg = A_norm h + b1
    k_gemm64<0, 0, false, false><<<gemmGrid, TB>>>(x, W1, b1, out, IN_DIM);
    k_aggregate<<<N_NODES, FDIM>>>(b1);

    // Layer 2: h = relu(agg) @ W2 ; agg = A_norm h + b2
    k_gemm64<1, 0, true, false><<<gemmGrid, TB>>>(x, W2, b2, out, HID_DIM);
    k_aggregate<<<N_NODES, FDIM>>>(b2);

    // Projection head: out = agg @ Wp + bp
    k_gemm64<1, 1, false, true><<<gemmGrid, TB>>>(x, Wp, bp, out, HID_DIM);
}

// round 11
// speedup vs baseline: 1.1990x; 1.1990x over previous
#include <cuda_runtime.h>
#include <cuda_bf16.h>
#include <cstdint>

// Problem constants (fixed-shape benchmark)
#define N_NODES 50000
#define N_EDGES 800000
#define IN_DIM  512
#define FDIM    256   // HID_DIM == OUT_DIM == 256

// ---------------------------------------------------------------------------
// Scratch (static __device__ — no allocation allowed)
// ---------------------------------------------------------------------------
__device__ __align__(128) float g_h[(size_t)N_NODES * FDIM];          // GEMM output (fp32)
__device__ __align__(128) __nv_bfloat16 g_xhi[(size_t)N_NODES * IN_DIM];
__device__ __align__(128) __nv_bfloat16 g_xlo[(size_t)N_NODES * IN_DIM];
__device__ __align__(128) __nv_bfloat16 g_ahi[(size_t)N_NODES * FDIM]; // split of aggregate output
__device__ __align__(128) __nv_bfloat16 g_alo[(size_t)N_NODES * FDIM];
__device__ __align__(128) __nv_bfloat16 g_w1h[IN_DIM * FDIM], g_w1l[IN_DIM * FDIM];
__device__ __align__(128) __nv_bfloat16 g_w2h[FDIM * FDIM],  g_w2l[FDIM * FDIM];
__device__ __align__(128) __nv_bfloat16 g_wph[FDIM * FDIM],  g_wpl[FDIM * FDIM];

__device__ __align__(128) float g_dis[N_NODES];   // deg^{-1/2}
__device__ int   g_deg[N_NODES];
__device__ int   g_off[N_NODES + 1];              // CSR row offsets (by dst)
__device__ int   g_cursor[N_NODES];
__device__ int   g_csr_src[N_EDGES];
__device__ float g_csr_coef[N_EDGES];

// ---------------------------------------------------------------------------
// CSR construction (cold path) — edge_index is INT32: ei[0:E)=src, ei[E:2E)=dst
// ---------------------------------------------------------------------------
__global__ void k_zero_deg() {
    int i = blockIdx.x * blockDim.x + threadIdx.x;
    if (i < N_NODES) g_deg[i] = 0;
}

__global__ void k_count_deg(const int* __restrict__ ei) {
    int e = blockIdx.x * blockDim.x + threadIdx.x;
    if (e < N_EDGES) {
        int d = ei[N_EDGES + e];
        if ((unsigned)d < (unsigned)N_NODES)
            atomicAdd(&g_deg[d], 1);
    }
}

__global__ __launch_bounds__(1024) void k_scan() {
    __shared__ int s[1024];
    __shared__ int carry_s;
    if (threadIdx.x == 0) carry_s = 0;
    __syncthreads();
    for (int base = 0; base < N_NODES; base += 1024) {
        int i = base + threadIdx.x;
        int v = (i < N_NODES) ? g_deg[i] : 0;
        s[threadIdx.x] = v;
        __syncthreads();
        #pragma unroll
        for (int ofs = 1; ofs < 1024; ofs <<= 1) {
            int t = (threadIdx.x >= ofs) ? s[threadIdx.x - ofs] : 0;
            __syncthreads();
            s[threadIdx.x] += t;
            __syncthreads();
        }
        if (i < N_NODES) {
            int excl = carry_s + s[threadIdx.x] - v;
            g_off[i]    = excl;
            g_cursor[i] = excl;
            g_dis[i]    = rsqrtf((float)v + 1.0f);
        }
        __syncthreads();
        if (threadIdx.x == 0) carry_s += s[1023];
        __syncthreads();
    }
    if (threadIdx.x == 0) g_off[N_NODES] = carry_s;
}

__global__ void k_place(const int* __restrict__ ei) {
    int e = blockIdx.x * blockDim.x + threadIdx.x;
    if (e < N_EDGES) {
        int s = ei[e];
        int d = ei[N_EDGES + e];
        if ((unsigned)s >= (unsigned)N_NODES || (unsigned)d >= (unsigned)N_NODES) return;
        int pos = atomicAdd(&g_cursor[d], 1);
        g_csr_src[pos]  = s;
        g_csr_coef[pos] = g_dis[s] * g_dis[d];
    }
}

// ---------------------------------------------------------------------------
// bf16 hi/lo split helpers + conversion kernels
// ---------------------------------------------------------------------------
__device__ __forceinline__ void split_bf16(float v, __nv_bfloat16& hi, __nv_bfloat16& lo) {
    hi = __float2bfloat16(v);
    lo = __float2bfloat16(v - __bfloat162float(hi));
}

__global__ void k_split_x(const float* __restrict__ x) {
    int i = blockIdx.x * blockDim.x + threadIdx.x;   // over N_NODES*IN_DIM/4
    if (i >= N_NODES * (IN_DIM / 4)) return;
    const float4 v = reinterpret_cast<const float4*>(x)[i];
    __nv_bfloat16 h[4], l[4];
    split_bf16(v.x, h[0], l[0]);
    split_bf16(v.y, h[1], l[1]);
    split_bf16(v.z, h[2], l[2]);
    split_bf16(v.w, h[3], l[3]);
    *reinterpret_cast<uint64_t*>(&g_xhi[(size_t)i * 4]) = *reinterpret_cast<uint64_t*>(h);
    *reinterpret_cast<uint64_t*>(&g_xlo[(size_t)i * 4]) = *reinterpret_cast<uint64_t*>(l);
}

template<int WSEL>
__global__ void k_split_w(const float* __restrict__ W, int n) {
    int i = blockIdx.x * blockDim.x + threadIdx.x;
    if (i >= n) return;
    __nv_bfloat16* hi = (WSEL == 0) ? g_w1h : (WSEL == 1) ? g_w2h : g_wph;
    __nv_bfloat16* lo = (WSEL == 0) ? g_w1l : (WSEL == 1) ? g_w2l : g_wpl;
    __nv_bfloat16 h, l;
    split_bf16(W[i], h, l);
    hi[i] = h; lo[i] = l;
}

// ---------------------------------------------------------------------------
// Aggregation (gather, no atomics, deterministic):
// acc = dis[i]^2 * h[i,f] + b[f] + sum_{e: dst=i} coef_e * h[src_e, f]
// then (optional relu) and write bf16 hi/lo split for the next GEMM.
// ---------------------------------------------------------------------------
template<bool RELU>
__global__ __launch_bounds__(FDIM) void k_aggregate(const float* __restrict__ bias) {
    const int i = blockIdx.x;
    const int f = threadIdx.x;
    const float di = g_dis[i];
    float acc = fmaf(di * di, g_h[(size_t)i * FDIM + f], bias[f]);
    const int e0 = g_off[i];
    const int e1 = g_off[i + 1];
    int e = e0;
    for (; e + 1 < e1; e += 2) {
        int   s0 = g_csr_src[e],  s1 = g_csr_src[e + 1];
        float c0 = g_csr_coef[e], c1 = g_csr_coef[e + 1];
        float v0 = g_h[(size_t)s0 * FDIM + f];
        float v1 = g_h[(size_t)s1 * FDIM + f];
        acc = fmaf(c0, v0, acc);
        acc = fmaf(c1, v1, acc);
    }
    if (e < e1)
        acc = fmaf(g_csr_coef[e], g_h[(size_t)g_csr_src[e] * FDIM + f], acc);
    if (RELU) acc = fmaxf(acc, 0.0f);
    __nv_bfloat16 h, l;
    split_bf16(acc, h, l);
    g_ahi[(size_t)i * FDIM + f] = h;
    g_alo[(size_t)i * FDIM + f] = l;
}

// ---------------------------------------------------------------------------
// Tensor-core GEMM: C[M=50000, 256] = A @ B (+bias), A/B in bf16 hi/lo split.
// C = Ahi*Bhi + Ahi*Blo + Alo*Bhi (fp32 accumulate, mma.sync m16n8k16).
// Block: 128(M) x 64(N), BK=32, 256 threads = 8 warps (4x2), warp = 32x32.
// ASEL: 0 = x split, 1 = aggregate split.  CSEL: 0 -> g_h, 1 -> Cp (+bias).
// ---------------------------------------------------------------------------
#define MMA16816(cf, a, b)                                                    \
    asm volatile("mma.sync.aligned.m16n8k16.row.col.f32.bf16.bf16.f32 "       \
                 "{%0,%1,%2,%3}, {%4,%5,%6,%7}, {%8,%9}, {%0,%1,%2,%3};"      \
                 : "+f"(cf[0]), "+f"(cf[1]), "+f"(cf[2]), "+f"(cf[3])         \
                 : "r"(a[0]), "r"(a[1]), "r"(a[2]), "r"(a[3]),                 \
                   "r"(b[0]), "r"(b[1]))

template<int ASEL, int CSEL, int K>
__global__ __launch_bounds__(256) void k_mma_gemm(const float* __restrict__ bias,
                                                  float* __restrict__ Cp)
{
    const __nv_bfloat16* __restrict__ Ahi = ASEL ? g_ahi : g_xhi;
    const __nv_bfloat16* __restrict__ Alo = ASEL ? g_alo : g_xlo;
    const __nv_bfloat16* __restrict__ Bhi = (K == 512) ? g_w1h : (CSEL ? g_wph : g_w2h);
    const __nv_bfloat16* __restrict__ Blo = (K == 512) ? g_w1l : (CSEL ? g_wpl : g_w2l);
    float* __restrict__ C = CSEL ? Cp : g_h;

    // +8 bf16 pad => 40 (row stride 80B: 16B-aligned, conflict-free frag loads)
    __shared__ __nv_bfloat16 Ah[128][40], Al[128][40];
    __shared__ __nv_bfloat16 Bh[64][40],  Bl[64][40];

    const int tid  = threadIdx.x;
    const int lane = tid & 31;
    const int warp = tid >> 5;
    const int wm = warp & 3;        // 0..3 -> 32-row slice
    const int wn = warp >> 2;       // 0..1 -> 32-col slice
    const int m0 = blockIdx.y * 128;
    const int n0 = blockIdx.x * 64;

    // loaders
    const int a_row = tid >> 1;            // 0..127
    const int a_kc  = (tid & 1) * 16;      // 0 or 16
    const int b_k   = tid >> 3;            // 0..31
    const int b_nc  = (tid & 7) * 8;       // 0..56

    const int gid = lane >> 2;             // 0..7
    const int qid = lane & 3;              // 0..3

    float c[2][4][4];
    #pragma unroll
    for (int mi = 0; mi < 2; mi++)
        #pragma unroll
        for (int ni = 0; ni < 4; ni++)
            #pragma unroll
            for (int j = 0; j < 4; j++) c[mi][ni][j] = 0.0f;

    #pragma unroll 1
    for (int k0 = 0; k0 < K; k0 += 32) {
        // ---- load A tile (128 x 32) hi+lo ----
        {
            int gr = m0 + a_row;
            uint4 vh0 = {0,0,0,0}, vh1 = {0,0,0,0}, vl0 = {0,0,0,0}, vl1 = {0,0,0,0};
            if (gr < N_NODES) {
                const uint4* ph = reinterpret_cast<const uint4*>(&Ahi[(size_t)gr * K + k0 + a_kc]);
                const uint4* pl = reinterpret_cast<const uint4*>(&Alo[(size_t)gr * K + k0 + a_kc]);
                vh0 = ph[0]; vh1 = ph[1];
                vl0 = pl[0]; vl1 = pl[1];
            }
            *reinterpret_cast<uint4*>(&Ah[a_row][a_kc])     = vh0;
            *reinterpret_cast<uint4*>(&Ah[a_row][a_kc + 8]) = vh1;
            *reinterpret_cast<uint4*>(&Al[a_row][a_kc])     = vl0;
            *reinterpret_cast<uint4*>(&Al[a_row][a_kc + 8]) = vl1;
        }
        // ---- load B tile (32 x 64) hi+lo, transposed to [n][k] ----
        {
            union { uint4 u; __nv_bfloat16 h[8]; } ubh, ubl;
            ubh.u = *reinterpret_cast<const uint4*>(&Bhi[(size_t)(k0 + b_k) * FDIM + n0 + b_nc]);
            ubl.u = *reinterpret_cast<const uint4*>(&Blo[(size_t)(k0 + b_k) * FDIM + n0 + b_nc]);
            #pragma unroll
            for (int j = 0; j < 8; j++) {
                Bh[b_nc + j][b_k] = ubh.h[j];
                Bl[b_nc + j][b_k] = ubl.h[j];
            }
        }
        __syncthreads();

        #pragma unroll
        for (int ks = 0; ks < 32; ks += 16) {
            uint32_t ah[2][4], al[2][4], bh[4][2], bl[4][2];
            const int kc = ks + qid * 2;
            #pragma unroll
            for (int mi = 0; mi < 2; mi++) {
                int r = wm * 32 + mi * 16 + gid;
                ah[mi][0] = *reinterpret_cast<const uint32_t*>(&Ah[r    ][kc    ]);
                ah[mi][1] = *reinterpret_cast<const uint32_t*>(&Ah[r + 8][kc    ]);
                ah[mi][2] = *reinterpret_cast<const uint32_t*>(&Ah[r    ][kc + 8]);
                ah[mi][3] = *reinterpret_cast<const uint32_t*>(&Ah[r + 8][kc + 8]);
                al[mi][0] = *reinterpret_cast<const uint32_t*>(&Al[r    ][kc    ]);
                al[mi][1] = *reinterpret_cast<const uint32_t*>(&Al[r + 8][kc    ]);
                al[mi][2] = *reinterpret_cast<const uint32_t*>(&Al[r    ][kc + 8]);
                al[mi][3] = *reinterpret_cast<const uint32_t*>(&Al[r + 8][kc + 8]);
            }
            #pragma unroll
            for (int ni = 0; ni < 4; ni++) {
                int nr = wn * 32 + ni * 8 + gid;
                bh[ni][0] = *reinterpret_cast<const uint32_t*>(&Bh[nr][kc    ]);
                bh[ni][1] = *reinterpret_cast<const uint32_t*>(&Bh[nr][kc + 8]);
                bl[ni][0] = *reinterpret_cast<const uint32_t*>(&Bl[nr][kc    ]);
                bl[ni][1] = *reinterpret_cast<const uint32_t*>(&Bl[nr][kc + 8]);
            }
            #pragma unroll
            for (int mi = 0; mi < 2; mi++)
                #pragma unroll
                for (int ni = 0; ni < 4; ni++) {
                    MMA16816(c[mi][ni], ah[mi], bh[ni]);
                    MMA16816(c[mi][ni], ah[mi], bl[ni]);
                    MMA16816(c[mi][ni], al[mi], bh[ni]);
                }
        }
        __syncthreads();
    }

    // ---- epilogue ----
    #pragma unroll
    for (int mi = 0; mi < 2; mi++) {
        int r0 = m0 + wm * 32 + mi * 16 + gid;
        #pragma unroll
        for (int ni = 0; ni < 4; ni++) {
            int col = n0 + wn * 32 + ni * 8 + qid * 2;
            float bx = 0.f, by = 0.f;
            if (CSEL) { bx = bias[col]; by = bias[col + 1]; }
            if (r0 < N_NODES) {
                float2 o = make_float2(c[mi][ni][0] + bx, c[mi][ni][1] + by);
                *reinterpret_cast<float2*>(&C[(size_t)r0 * FDIM + col]) = o;
            }
            if (r0 + 8 < N_NODES) {
                float2 o = make_float2(c[mi][ni][2] + bx, c[mi][ni][3] + by);
                *reinterpret_cast<float2*>(&C[(size_t)(r0 + 8) * FDIM + col]) = o;
            }
        }
    }
}

// ---------------------------------------------------------------------------
// Launch — kernel launches ONLY (graph-capturable, allocation-free)
// ---------------------------------------------------------------------------
extern "C" void kernel_launch(void* const* d_in, const int* in_sizes, int n_in,
                              void* d_out, int out_size)
{
    const float* x  = (const float*)d_in[0];
    const int*   ei = (const int*)d_in[1];     // int32 (JAX x64 disabled)
    const float* W1 = (const float*)d_in[2];
    const float* b1 = (const float*)d_in[3];
    const float* W2 = (const float*)d_in[4];
    const float* b2 = (const float*)d_in[5];
    const float* Wp = (const float*)d_in[6];
    const float* bp = (const float*)d_in[7];
    float* out = (float*)d_out;

    const int TB = 256;
    const int nodeBlocks = (N_NODES + TB - 1) / TB;
    const int edgeBlocks = (N_EDGES + TB - 1) / TB;
    dim3 gemmGrid(FDIM / 64, (N_NODES + 127) / 128);

    // CSR build + normalization
    k_zero_deg<<<nodeBlocks, TB>>>();
    k_count_deg<<<edgeBlocks, TB>>>(ei);
    k_scan<<<1, 1024>>>();
    k_place<<<edgeBlocks, TB>>>(ei);

    // bf16 hi/lo splits of inputs + weights
    k_split_x<<<(N_NODES * (IN_DIM / 4) + TB - 1) / TB, TB>>>(x);
    k_split_w<0><<<(IN_DIM * FDIM + TB - 1) / TB, TB>>>(W1, IN_DIM * FDIM);
    k_split_w<1><<<(FDIM * FDIM + TB - 1) / TB, TB>>>(W2, FDIM * FDIM);
    k_split_w<2><<<(FDIM * FDIM + TB - 1) / TB, TB>>>(Wp, FDIM * FDIM);

    // Layer 1: h = x @ W1 ; agg1 = relu(A_norm h + b1) -> split
    k_mma_gemm<0, 0, IN_DIM><<<gemmGrid, TB>>>(b1, nullptr);
    k_aggregate<true><<<N_NODES, FDIM>>>(b1);

    // Layer 2: h = agg1 @ W2 ; agg2 = A_norm h + b2 -> split
    k_mma_gemm<1, 0, FDIM><<<gemmGrid, TB>>>(b2, nullptr);
    k_aggregate<false><<<N_NODES, FDIM>>>(b2);

    // Projection: out = agg2 @ Wp + bp
    k_mma_gemm<1, 1, FDIM><<<gemmGrid, TB>>>(bp, out);
}

// round 13
// speedup vs baseline: 1.6260x; 1.3561x over previous
#include <cuda_runtime.h>
#include <cuda_bf16.h>
#include <cstdint>

// Problem constants (fixed-shape benchmark)
#define N_NODES 50000
#define N_EDGES 800000
#define IN_DIM  512
#define FDIM    256   // HID_DIM == OUT_DIM == 256

// ---------------------------------------------------------------------------
// Scratch (static __device__ — no allocation allowed)
// ---------------------------------------------------------------------------
__device__ __align__(128) float g_h[(size_t)N_NODES * FDIM];          // GEMM output (fp32)
__device__ __align__(128) __nv_bfloat16 g_xhi[(size_t)N_NODES * IN_DIM];
__device__ __align__(128) __nv_bfloat16 g_xlo[(size_t)N_NODES * IN_DIM];
__device__ __align__(128) __nv_bfloat16 g_ahi[(size_t)N_NODES * FDIM];
__device__ __align__(128) __nv_bfloat16 g_alo[(size_t)N_NODES * FDIM];
__device__ __align__(128) __nv_bfloat16 g_w1h[IN_DIM * FDIM], g_w1l[IN_DIM * FDIM];
__device__ __align__(128) __nv_bfloat16 g_w2h[FDIM * FDIM],  g_w2l[FDIM * FDIM];
__device__ __align__(128) __nv_bfloat16 g_wph[FDIM * FDIM],  g_wpl[FDIM * FDIM];

__device__ __align__(128) float g_dis[N_NODES];
__device__ int   g_deg[N_NODES];
__device__ int   g_off[N_NODES + 1];
__device__ int   g_cursor[N_NODES];
__device__ int   g_csr_src[N_EDGES];
__device__ float g_csr_coef[N_EDGES];

// ---------------------------------------------------------------------------
// CSR construction (cold path) — edge_index INT32: ei[0:E)=src, ei[E:2E)=dst
// ---------------------------------------------------------------------------
__global__ void k_zero_deg() {
    int i = blockIdx.x * blockDim.x + threadIdx.x;
    if (i < N_NODES) g_deg[i] = 0;
}

__global__ void k_count_deg(const int* __restrict__ ei) {
    int e = blockIdx.x * blockDim.x + threadIdx.x;
    if (e < N_EDGES) {
        int d = ei[N_EDGES + e];
        if ((unsigned)d < (unsigned)N_NODES)
            atomicAdd(&g_deg[d], 1);
    }
}

__global__ __launch_bounds__(1024) void k_scan() {
    __shared__ int s[1024];
    __shared__ int carry_s;
    if (threadIdx.x == 0) carry_s = 0;
    __syncthreads();
    for (int base = 0; base < N_NODES; base += 1024) {
        int i = base + threadIdx.x;
        int v = (i < N_NODES) ? g_deg[i] : 0;
        s[threadIdx.x] = v;
        __syncthreads();
        #pragma unroll
        for (int ofs = 1; ofs < 1024; ofs <<= 1) {
            int t = (threadIdx.x >= ofs) ? s[threadIdx.x - ofs] : 0;
            __syncthreads();
            s[threadIdx.x] += t;
            __syncthreads();
        }
        if (i < N_NODES) {
            int excl = carry_s + s[threadIdx.x] - v;
            g_off[i]    = excl;
            g_cursor[i] = excl;
            g_dis[i]    = rsqrtf((float)v + 1.0f);
        }
        __syncthreads();
        if (threadIdx.x == 0) carry_s += s[1023];
        __syncthreads();
    }
    if (threadIdx.x == 0) g_off[N_NODES] = carry_s;
}

__global__ void k_place(const int* __restrict__ ei) {
    int e = blockIdx.x * blockDim.x + threadIdx.x;
    if (e < N_EDGES) {
        int s = ei[e];
        int d = ei[N_EDGES + e];
        if ((unsigned)s >= (unsigned)N_NODES || (unsigned)d >= (unsigned)N_NODES) return;
        int pos = atomicAdd(&g_cursor[d], 1);
        g_csr_src[pos]  = s;
        g_csr_coef[pos] = g_dis[s] * g_dis[d];
    }
}

// ---------------------------------------------------------------------------
// bf16 hi/lo split helpers + conversion kernels
// ---------------------------------------------------------------------------
__device__ __forceinline__ void split_bf16(float v, __nv_bfloat16& hi, __nv_bfloat16& lo) {
    hi = __float2bfloat16(v);
    lo = __float2bfloat16(v - __bfloat162float(hi));
}

__global__ void k_split_x(const float* __restrict__ x) {
    int i = blockIdx.x * blockDim.x + threadIdx.x;
    if (i >= N_NODES * (IN_DIM / 4)) return;
    const float4 v = reinterpret_cast<const float4*>(x)[i];
    __nv_bfloat16 h[4], l[4];
    split_bf16(v.x, h[0], l[0]);
    split_bf16(v.y, h[1], l[1]);
    split_bf16(v.z, h[2], l[2]);
    split_bf16(v.w, h[3], l[3]);
    *reinterpret_cast<uint64_t*>(&g_xhi[(size_t)i * 4]) = *reinterpret_cast<uint64_t*>(h);
    *reinterpret_cast<uint64_t*>(&g_xlo[(size_t)i * 4]) = *reinterpret_cast<uint64_t*>(l);
}

template<int WSEL>
__global__ void k_split_w(const float* __restrict__ W, int n) {
    int i = blockIdx.x * blockDim.x + threadIdx.x;
    if (i >= n) return;
    __nv_bfloat16* hi = (WSEL == 0) ? g_w1h : (WSEL == 1) ? g_w2h : g_wph;
    __nv_bfloat16* lo = (WSEL == 0) ? g_w1l : (WSEL == 1) ? g_w2l : g_wpl;
    __nv_bfloat16 h, l;
    split_bf16(W[i], h, l);
    hi[i] = h; lo[i] = l;
}

// ---------------------------------------------------------------------------
// Aggregation (gather, no atomics, deterministic), 4-way unrolled for MLP.
// ---------------------------------------------------------------------------
template<bool RELU>
__global__ __launch_bounds__(FDIM) void k_aggregate(const float* __restrict__ bias) {
    const int i = blockIdx.x;
    const int f = threadIdx.x;
    const float di = g_dis[i];
    float acc = fmaf(di * di, g_h[(size_t)i * FDIM + f], bias[f]);
    const int e0 = g_off[i];
    const int e1 = g_off[i + 1];
    int e = e0;
    for (; e + 3 < e1; e += 4) {
        int   s0 = g_csr_src[e],      s1 = g_csr_src[e + 1];
        int   s2 = g_csr_src[e + 2],  s3 = g_csr_src[e + 3];
        float c0 = g_csr_coef[e],     c1 = g_csr_coef[e + 1];
        float c2 = g_csr_coef[e + 2], c3 = g_csr_coef[e + 3];
        float v0 = g_h[(size_t)s0 * FDIM + f];
        float v1 = g_h[(size_t)s1 * FDIM + f];
        float v2 = g_h[(size_t)s2 * FDIM + f];
        float v3 = g_h[(size_t)s3 * FDIM + f];
        acc = fmaf(c0, v0, acc);
        acc = fmaf(c1, v1, acc);
        acc = fmaf(c2, v2, acc);
        acc = fmaf(c3, v3, acc);
    }
    for (; e < e1; e++)
        acc = fmaf(g_csr_coef[e], g_h[(size_t)g_csr_src[e] * FDIM + f], acc);
    if (RELU) acc = fmaxf(acc, 0.0f);
    __nv_bfloat16 h, l;
    split_bf16(acc, h, l);
    g_ahi[(size_t)i * FDIM + f] = h;
    g_alo[(size_t)i * FDIM + f] = l;
}

// ---------------------------------------------------------------------------
// Tensor-core GEMM, ldmatrix + cp.async 2-stage pipeline, dynamic smem.
// C[M=50000, 256] = A @ B (+bias), 3-term bf16 split (AhBh + AhBl + AlBh).
// Block 128(M) x 64(N), BK=32, 256 thr = 8 warps (4x2), warp tile 32x32.
// A smem [m][k], stride 40 bf16 = 80 B (16B-aligned rows; 8-row LDSM phase
//   hits banks {0,20,8,28,16,4,24,12}*4 => all 32 banks, conflict-free).
// B smem [k][n], stride 72 bf16 = 144 B (16B-aligned, conflict-free trans).
// ---------------------------------------------------------------------------
#define A_STRIDE   40
#define A_BUF_BYTES (128 * A_STRIDE * 2)          // 10240
#define B_STRIDE   72
#define OFF_AH     0
#define OFF_AL     (2 * A_BUF_BYTES)              // 20480
#define OFF_BH     (4 * A_BUF_BYTES)              // 40960
#define OFF_BL     (OFF_BH + 32 * B_STRIDE * 2)   // 45568
#define SMEM_BYTES (OFF_BL + 32 * B_STRIDE * 2)   // 50176

#define MMA16816(cf, a, b)                                                    \
    asm volatile("mma.sync.aligned.m16n8k16.row.col.f32.bf16.bf16.f32 "       \
                 "{%0,%1,%2,%3}, {%4,%5,%6,%7}, {%8,%9}, {%0,%1,%2,%3};"      \
                 : "+f"(cf[0]), "+f"(cf[1]), "+f"(cf[2]), "+f"(cf[3])         \
                 : "r"(a[0]), "r"(a[1]), "r"(a[2]), "r"(a[3]),                 \
                   "r"(b[0]), "r"(b[1]))

#define LDSM_X4(d, addr)                                                       \
    asm volatile("ldmatrix.sync.aligned.m8n8.x4.shared.b16 {%0,%1,%2,%3}, [%4];" \
                 : "=r"(d[0]), "=r"(d[1]), "=r"(d[2]), "=r"(d[3]) : "r"(addr))

#define LDSM_X4T(d0, d1, d2, d3, addr)                                         \
    asm volatile("ldmatrix.sync.aligned.m8n8.x4.trans.shared.b16 {%0,%1,%2,%3}, [%4];" \
                 : "=r"(d0), "=r"(d1), "=r"(d2), "=r"(d3) : "r"(addr))

#define CP_ASYNC16(s, g) \
    asm volatile("cp.async.cg.shared.global [%0], [%1], 16;" :: "r"(s), "l"(g))
#define CP_COMMIT()  asm volatile("cp.async.commit_group;")
#define CP_WAIT0()   asm volatile("cp.async.wait_group 0;")
#define CP_WAIT1()   asm volatile("cp.async.wait_group 1;")

__device__ __forceinline__ uint32_t s2u(const void* p) {
    return (uint32_t)__cvta_generic_to_shared(p);
}

template<int ASEL, int CSEL, int K>
__global__ __launch_bounds__(256) void k_mma_gemm(const float* __restrict__ bias,
                                                  float* __restrict__ Cp)
{
    const __nv_bfloat16* __restrict__ Ahi = ASEL ? g_ahi : g_xhi;
    const __nv_bfloat16* __restrict__ Alo = ASEL ? g_alo : g_xlo;
    const __nv_bfloat16* __restrict__ Bhi = (K == 512) ? g_w1h : (CSEL ? g_wph : g_w2h);
    const __nv_bfloat16* __restrict__ Blo = (K == 512) ? g_w1l : (CSEL ? g_wpl : g_w2l);
    float* __restrict__ C = CSEL ? Cp : g_h;

    extern __shared__ char smem[];
    const uint32_t sb = s2u(smem);
    __nv_bfloat16* BhS = reinterpret_cast<__nv_bfloat16*>(smem + OFF_BH);
    __nv_bfloat16* BlS = reinterpret_cast<__nv_bfloat16*>(smem + OFF_BL);

    const int tid  = threadIdx.x;
    const int lane = tid & 31;
    const int warp = tid >> 5;
    const int wm = warp & 3;
    const int wn = warp >> 2;
    const int m0 = blockIdx.y * 128;
    const int n0 = blockIdx.x * 64;
    const int gid = lane >> 2;
    const int qid = lane & 3;

    // ---- A cp.async indexing: thread -> (row, 32B half-row) ----
    const int ar    = tid >> 1;
    const int ahalf = (tid & 1) * 16;                       // bf16 elements
    int gr = m0 + ar; if (gr > N_NODES - 1) gr = N_NODES - 1;
    const __nv_bfloat16* gAh = &Ahi[(size_t)gr * K + ahalf];
    const __nv_bfloat16* gAl = &Alo[(size_t)gr * K + ahalf];
    const uint32_t sAh0 = sb + OFF_AH + (uint32_t)(ar * A_STRIDE + ahalf) * 2;
    const uint32_t sAl0 = sb + OFF_AL + (uint32_t)(ar * A_STRIDE + ahalf) * 2;

    // ---- B staging: thread -> (k row, 16B of n), register double-buffer ----
    const int bk = tid >> 3;
    const int bn = (tid & 7) * 8;
    const __nv_bfloat16* gBh = &Bhi[(size_t)bk * FDIM + n0 + bn];
    const __nv_bfloat16* gBl = &Blo[(size_t)bk * FDIM + n0 + bn];

    // ldmatrix lane addressing
    const int aLaneRow  = lane & 15;
    const int aLaneKOfs = (lane >> 4) * 8;
    const int bLaneRow  = (lane & 7) + (lane & 8);
    const int bLaneNOfs = (lane >> 4) * 8;

    float c[2][4][4];
    #pragma unroll
    for (int mi = 0; mi < 2; mi++)
        #pragma unroll
        for (int ni = 0; ni < 4; ni++)
            #pragma unroll
            for (int j = 0; j < 4; j++) c[mi][ni][j] = 0.0f;

    const int nIter = K / 32;

    // prologue: stage-0 A copy + B regs for iter 0
    CP_ASYNC16(sAh0,      (const char*)gAh);
    CP_ASYNC16(sAh0 + 16, (const char*)gAh + 16);
    CP_ASYNC16(sAl0,      (const char*)gAl);
    CP_ASYNC16(sAl0 + 16, (const char*)gAl + 16);
    CP_COMMIT();
    uint4 curBh = *reinterpret_cast<const uint4*>(gBh);
    uint4 curBl = *reinterpret_cast<const uint4*>(gBl);

    #pragma unroll 1
    for (int i = 0; i < nIter; i++) {
        const int st = i & 1;

        // store B tile for this iteration (safe: barrier ended prev iter)
        *reinterpret_cast<uint4*>(&BhS[bk * B_STRIDE + bn]) = curBh;
        *reinterpret_cast<uint4*>(&BlS[bk * B_STRIDE + bn]) = curBl;

        uint4 nxtBh, nxtBl;
        if (i + 1 < nIter) {
            const int koff = (i + 1) * 32;                  // elements
            const uint32_t sOfs = (uint32_t)(st ^ 1) * A_BUF_BYTES;
            CP_ASYNC16(sAh0 + sOfs,      (const char*)(gAh + koff));
            CP_ASYNC16(sAh0 + sOfs + 16, (const char*)(gAh + koff) + 16);
            CP_ASYNC16(sAl0 + sOfs,      (const char*)(gAl + koff));
            CP_ASYNC16(sAl0 + sOfs + 16, (const char*)(gAl + koff) + 16);
            CP_COMMIT();
            nxtBh = *reinterpret_cast<const uint4*>(gBh + (size_t)koff * FDIM);
            nxtBl = *reinterpret_cast<const uint4*>(gBl + (size_t)koff * FDIM);
            CP_WAIT1();
        } else {
            CP_WAIT0();
        }
        __syncthreads();

        #pragma unroll
        for (int ks = 0; ks < 32; ks += 16) {
            uint32_t ah[2][4], al[2][4], bh[4][2], bl[4][2];
            #pragma unroll
            for (int mi = 0; mi < 2; mi++) {
                const int r = wm * 32 + mi * 16 + aLaneRow;
                const uint32_t ofs = (uint32_t)st * A_BUF_BYTES
                                   + (uint32_t)(r * A_STRIDE + ks + aLaneKOfs) * 2;
                LDSM_X4(ah[mi], sb + OFF_AH + ofs);
                LDSM_X4(al[mi], sb + OFF_AL + ofs);
            }
            #pragma unroll
            for (int p = 0; p < 2; p++) {
                const int nb = wn * 32 + p * 16;
                const uint32_t ofs = (uint32_t)((ks + bLaneRow) * B_STRIDE + nb + bLaneNOfs) * 2;
                LDSM_X4T(bh[2*p][0], bh[2*p][1], bh[2*p+1][0], bh[2*p+1][1], sb + OFF_BH + ofs);
                LDSM_X4T(bl[2*p][0], bl[2*p][1], bl[2*p+1][0], bl[2*p+1][1], sb + OFF_BL + ofs);
            }
            #pragma unroll
            for (int mi = 0; mi < 2; mi++)
                #pragma unroll
                for (int ni = 0; ni < 4; ni++) {
                    MMA16816(c[mi][ni], ah[mi], bh[ni]);
                    MMA16816(c[mi][ni], ah[mi], bl[ni]);
                    MMA16816(c[mi][ni], al[mi], bh[ni]);
                }
        }
        __syncthreads();

        curBh = nxtBh;
        curBl = nxtBl;
    }

    // ---- epilogue ----
    #pragma unroll
    for (int mi = 0; mi < 2; mi++) {
        int r0 = m0 + wm * 32 + mi * 16 + gid;
        #pragma unroll
        for (int ni = 0; ni < 4; ni++) {
            int col = n0 + wn * 32 + ni * 8 + qid * 2;
            float bx = 0.f, by = 0.f;
            if (CSEL) { bx = bias[col]; by = bias[col + 1]; }
            if (r0 < N_NODES) {
                float2 o = make_float2(c[mi][ni][0] + bx, c[mi][ni][1] + by);
                *reinterpret_cast<float2*>(&C[(size_t)r0 * FDIM + col]) = o;
            }
            if (r0 + 8 < N_NODES) {
                float2 o = make_float2(c[mi][ni][2] + bx, c[mi][ni][3] + by);
                *reinterpret_cast<float2*>(&C[(size_t)(r0 + 8) * FDIM + col]) = o;
            }
        }
    }
}

// ---------------------------------------------------------------------------
// Launch — kernel launches ONLY (graph-capturable, allocation-free)
// ---------------------------------------------------------------------------
extern "C" void kernel_launch(void* const* d_in, const int* in_sizes, int n_in,
                              void* d_out, int out_size)
{
    const float* x  = (const float*)d_in[0];
    const int*   ei = (const int*)d_in[1];     // int32 (JAX x64 disabled)
    const float* W1 = (const float*)d_in[2];
    const float* b1 = (const float*)d_in[3];
    const float* W2 = (const float*)d_in[4];
    const float* b2 = (const float*)d_in[5];
    const float* Wp = (const float*)d_in[6];
    const float* bp = (const float*)d_in[7];
    float* out = (float*)d_out;

    // Raise dynamic smem limit for the GEMM instantiations (host attr set;
    // not a stream op — legal under graph capture).
    static bool attr_done = false;
    if (!attr_done) {
        cudaFuncSetAttribute(k_mma_gemm<0, 0, IN_DIM>,
                             cudaFuncAttributeMaxDynamicSharedMemorySize, SMEM_BYTES);
        cudaFuncSetAttribute(k_mma_gemm<1, 0, FDIM>,
                             cudaFuncAttributeMaxDynamicSharedMemorySize, SMEM_BYTES);
        cudaFuncSetAttribute(k_mma_gemm<1, 1, FDIM>,
                             cudaFuncAttributeMaxDynamicSharedMemorySize, SMEM_BYTES);
        attr_done = true;
    }

    const int TB = 256;
    const int nodeBlocks = (N_NODES + TB - 1) / TB;
    const int edgeBlocks = (N_EDGES + TB - 1) / TB;
    dim3 gemmGrid(FDIM / 64, (N_NODES + 127) / 128);

    // CSR build + normalization
    k_zero_deg<<<nodeBlocks, TB>>>();
    k_count_deg<<<edgeBlocks, TB>>>(ei);
    k_scan<<<1, 1024>>>();
    k_place<<<edgeBlocks, TB>>>(ei);

    // bf16 hi/lo splits of inputs + weights
    k_split_x<<<(N_NODES * (IN_DIM / 4) + TB - 1) / TB, TB>>>(x);
    k_split_w<0><<<(IN_DIM * FDIM + TB - 1) / TB, TB>>>(W1, IN_DIM * FDIM);
    k_split_w<1><<<(FDIM * FDIM + TB - 1) / TB, TB>>>(W2, FDIM * FDIM);
    k_split_w<2><<<(FDIM * FDIM + TB - 1) / TB, TB>>>(Wp, FDIM * FDIM);

    // Layer 1: h = x @ W1 ; agg1 = relu(A_norm h + b1) -> split
    k_mma_gemm<0, 0, IN_DIM><<<gemmGrid, TB, SMEM_BYTES>>>(b1, nullptr);
    k_aggregate<true><<<N_NODES, FDIM>>>(b1);

    // Layer 2: h = agg1 @ W2 ; agg2 = A_norm h + b2 -> split
    k_mma_gemm<1, 0, FDIM><<<gemmGrid, TB, SMEM_BYTES>>>(b2, nullptr);
    k_aggregate<false><<<N_NODES, FDIM>>>(b2);

    // Projection: out = agg2 @ Wp + bp
    k_mma_gemm<1, 1, FDIM><<<gemmGrid, TB, SMEM_BYTES>>>(bp, out);
}